// round 13
// baseline (speedup 1.0000x reference)
#include <cuda_runtime.h>
#include <cuda_fp16.h>
#include <cstdint>
#include <math.h>

typedef __half fp16;

static constexpr int Bb = 8, Nn = 2048, Mm = 2048, Cc = 512;

// ---------------- scratch (__device__ globals; no allocations) ----------------
__device__ float S_buf [(size_t)Bb * Nn * Mm];          // scores fp32 (128 MiB)
__device__ fp16  P_buf [(size_t)Bb * Nn * Mm];          // softmax probs (single fp16)
__device__ fp16  dech_buf[(size_t)Bb * Nn * Cc], decl_buf[(size_t)Bb * Nn * Cc];
__device__ fp16  ench_buf[(size_t)Bb * Mm * Cc], encl_buf[(size_t)Bb * Mm * Cc];
__device__ float Vf_buf [(size_t)Bb * Mm * Cc];         // enc@Wv+bv fp32
__device__ fp16  VT_buf [(size_t)Bb * Cc * Mm];         // V^T single fp16
__device__ fp16  G_buf[(size_t)Bb * Nn * Cc];           // gated, single fp16
__device__ fp16  H_buf[(size_t)Bb * Nn * Cc];           // relu(fc1), single fp16
__device__ fp16  WvT_buf[Cc * Cc];
__device__ fp16  W1T_buf[Cc * Cc];
__device__ fp16  W2T_buf[Cc * Cc];

// ---------------- arch-neutral PTX helpers ----------------
__device__ __forceinline__ uint32_t smem_u32(const void* p) {
    uint32_t a;
    asm("{ .reg .u64 t; cvta.to.shared.u64 t, %1; cvt.u32.u64 %0, t; }" : "=r"(a) : "l"(p));
    return a;
}
__device__ __forceinline__ void cp_async16(uint32_t dst, const void* src) {
    asm volatile("cp.async.cg.shared.global [%0], [%1], 16;" :: "r"(dst), "l"(src) : "memory");
}
__device__ __forceinline__ void cp_commit() { asm volatile("cp.async.commit_group;" ::: "memory"); }
template <int N> __device__ __forceinline__ void cp_wait() {
    asm volatile("cp.async.wait_group %0;" :: "n"(N) : "memory");
}
__device__ __forceinline__ void ldsm_x4(uint32_t* r, uint32_t addr) {
    asm volatile("ldmatrix.sync.aligned.m8n8.x4.shared.b16 {%0,%1,%2,%3}, [%4];"
        : "=r"(r[0]), "=r"(r[1]), "=r"(r[2]), "=r"(r[3]) : "r"(addr));
}
__device__ __forceinline__ void mma16816(float* c, const uint32_t* a, const uint32_t* b) {
    asm volatile("mma.sync.aligned.m16n8k16.row.col.f32.f16.f16.f32 "
        "{%0,%1,%2,%3}, {%4,%5,%6,%7}, {%8,%9}, {%0,%1,%2,%3};"
        : "+f"(c[0]), "+f"(c[1]), "+f"(c[2]), "+f"(c[3])
        : "r"(a[0]), "r"(a[1]), "r"(a[2]), "r"(a[3]), "r"(b[0]), "r"(b[1]));
}
__device__ __forceinline__ float tanh_approx(float x) {
    float r;
    asm("tanh.approx.f32 %0, %1;" : "=f"(r) : "f"(x));
    return r;
}
// 64B-row swizzle: logical chunk c (0..3) of row r -> phys chunk c ^ ((r>>1)&3)
__device__ __forceinline__ uint32_t sw64(int r, int c) {
    return (uint32_t)r * 64u + (uint32_t)((c ^ ((r >> 1) & 3)) << 4);
}

// ---------------- conversion / transpose kernels ----------------
__global__ void split2_kernel(const float* __restrict__ inA, fp16* __restrict__ ohA, fp16* __restrict__ olA,
                              const float* __restrict__ inB, fp16* __restrict__ ohB, fp16* __restrict__ olB,
                              size_t n4) {
    size_t i = (size_t)blockIdx.x * blockDim.x + threadIdx.x;
    if (i >= n4) return;
    const float* in = blockIdx.y ? inB : inA;
    fp16* oh = blockIdx.y ? ohB : ohA;
    fp16* ol = blockIdx.y ? olB : olA;
    float4 v = ((const float4*)in)[i];
    fp16 h0 = __float2half_rn(v.x), h1 = __float2half_rn(v.y);
    fp16 h2 = __float2half_rn(v.z), h3 = __float2half_rn(v.w);
    ((__half2*)oh)[2 * i]     = __half2(h0, h1);
    ((__half2*)oh)[2 * i + 1] = __half2(h2, h3);
    ((__half2*)ol)[2 * i] = __half2(
        __float2half_rn(v.x - __half2float(h0)), __float2half_rn(v.y - __half2float(h1)));
    ((__half2*)ol)[2 * i + 1] = __half2(
        __float2half_rn(v.z - __half2float(h2)), __float2half_rn(v.w - __half2float(h3)));
}

// out[c][r] = in[r][c]
__global__ void transpose_fp16(const float* __restrict__ in, fp16* __restrict__ oh,
                               int rows, int cols, size_t ibs, size_t obs) {
    __shared__ float t[32][33];
    const float* I = in + (size_t)blockIdx.z * ibs;
    fp16* OH = oh + (size_t)blockIdx.z * obs;
    int c0 = blockIdx.x * 32, r0 = blockIdx.y * 32;
    int tx = threadIdx.x, ty = threadIdx.y;
    #pragma unroll
    for (int k = 0; k < 4; k++)
        t[ty + 8 * k][tx] = I[(size_t)(r0 + ty + 8 * k) * cols + c0 + tx];
    __syncthreads();
    #pragma unroll
    for (int k = 0; k < 4; k++) {
        float v = t[tx][ty + 8 * k];
        OH[(size_t)(c0 + ty + 8 * k) * rows + r0 + tx] = __float2half_rn(v);
    }
}

// ---------------- nonstandard masked softmax: S fp32 -> P fp16 ----------------
__global__ __launch_bounds__(256) void softmax_kernel(const float* __restrict__ Sb,
                                                      fp16* __restrict__ Pp) {
    const float* S = Sb + (size_t)blockIdx.x * Mm;
    fp16* P = Pp + (size_t)blockIdx.x * Mm;
    const int tid = threadIdx.x;

    float4 u0 = *(const float4*)&S[tid * 8];
    float4 u1 = *(const float4*)&S[tid * 8 + 4];
    float v[8] = {u0.x, u0.y, u0.z, u0.w, u1.x, u1.y, u1.z, u1.w};

    float mx = v[0];
    #pragma unroll
    for (int i = 1; i < 8; i++) mx = fmaxf(mx, v[i]);
    #pragma unroll
    for (int o = 16; o > 0; o >>= 1) mx = fmaxf(mx, __shfl_xor_sync(0xffffffffu, mx, o));

    __shared__ float red[8];
    const int wid = tid >> 5, lid = tid & 31;
    if (lid == 0) red[wid] = mx;
    __syncthreads();
    float rmax = red[0];
    #pragma unroll
    for (int w = 1; w < 8; w++) rmax = fmaxf(rmax, red[w]);
    __syncthreads();

    float e[8];
    float s = 0.f;
    #pragma unroll
    for (int i = 0; i < 8; i++) { e[i] = __expf(v[i] - rmax); s += e[i]; }
    #pragma unroll
    for (int o = 16; o > 0; o >>= 1) s += __shfl_xor_sync(0xffffffffu, s, o);
    if (lid == 0) red[wid] = s;
    __syncthreads();
    float tot = 0.f;
    #pragma unroll
    for (int w = 0; w < 8; w++) tot += red[w];
    const float inv = 1.f / tot;

    fp16 p[8];
    #pragma unroll
    for (int i = 0; i < 8; i++)
        p[i] = __float2half_rn((v[i] != 0.f) ? e[i] * inv : 0.f);
    *(uint4*)&P[tid * 8] = *(uint4*)p;
}

// ---------------- 3-term scores GEMM: 128x128 tile, 256 threads -------------
// S[128,128] = (dec x enc^T) * mask. Warp tile 32x64 (4x2 warp grid).
// Per SM-stage: tensor 1536 cyc vs LDSM 768 cyc -> tensor-bound.
static constexpr int SC_STAGE = 32768;         // Ah8K | Al8K | Bh8K | Bl8K
static constexpr int SM_SC = 3 * SC_STAGE;     // 98304; 2 CTAs/SM

__global__ __launch_bounds__(256) void score128(
    const fp16* __restrict__ Ah, const fp16* __restrict__ Al,
    const fp16* __restrict__ Bh, const fp16* __restrict__ Bl,
    const float* __restrict__ mask_, float* __restrict__ S_)
{
    extern __shared__ char smem[];
    const uint32_t sb = smem_u32(smem);
    const int tid = threadIdx.x;
    const int wid = tid >> 5, lane = tid & 31;
    const int tC = blockIdx.x, tR = blockIdx.y, bz = blockIdx.z;
    constexpr int NK = Cc / 32;    // 16

    const size_t ab = (size_t)bz * Nn * Cc, bb = (size_t)bz * Mm * Cc;
    const fp16* A0h = Ah + ab + (size_t)(tR * 128) * Cc;
    const fp16* A0l = Al + ab + (size_t)(tR * 128) * Cc;
    const fp16* B0h = Bh + bb + (size_t)(tC * 128) * Cc;
    const fp16* B0l = Bl + bb + (size_t)(tC * 128) * Cc;
    const fp16* bufs[4] = {A0h, A0l, B0h, B0l};

    auto load_stage = [&](int ks, int st) {
        const uint32_t base = sb + st * SC_STAGE;
        const int k0 = ks * 32;
        #pragma unroll
        for (int j = 0; j < 8; j++) {
            const int id = tid + j * 256;        // 0..2047
            const int comp = id >> 9;
            const int idx = id & 511;
            const int r = idx >> 2, c = idx & 3;
            cp_async16(base + comp * 8192 + sw64(r, c),
                       bufs[comp] + (size_t)r * Cc + k0 + c * 8);
        }
        cp_commit();
    };

    const int m0 = (wid & 3) * 32;     // 4 warps over 128 rows
    const int n0 = (wid >> 2) * 64;    // 2 warps over 128 cols

    float acc[2][8][4];
    #pragma unroll
    for (int mt = 0; mt < 2; mt++)
        #pragma unroll
        for (int nt = 0; nt < 8; nt++)
            #pragma unroll
            for (int q = 0; q < 4; q++) acc[mt][nt][q] = 0.f;

    load_stage(0, 0);
    load_stage(1, 1);

    for (int ks = 0; ks < NK; ks++) {
        if (ks + 1 < NK) cp_wait<1>(); else cp_wait<0>();
        __syncthreads();
        if (ks + 2 < NK) load_stage(ks + 2, (ks + 2) % 3);

        const uint32_t base = sb + (ks % 3) * SC_STAGE;
        #pragma unroll
        for (int kk = 0; kk < 2; kk++) {
            const int c0 = kk * 2;
            uint32_t ah[2][4], al[2][4];
            #pragma unroll
            for (int mt = 0; mt < 2; mt++) {
                const int row = m0 + mt * 16 + (lane & 15);
                const int ch = c0 + (lane >> 4);
                const uint32_t ad = base + sw64(row, ch);
                ldsm_x4(ah[mt], ad);
                ldsm_x4(al[mt], ad + 8192);
            }
            // B groups loaded and consumed one at a time (keeps regs low)
            #pragma unroll
            for (int g = 0; g < 4; g++) {
                const int row = n0 + g * 16 + ((lane >> 4) << 3) + (lane & 7);
                const int ch = c0 + ((lane >> 3) & 1);
                const uint32_t bd = base + 16384 + sw64(row, ch);
                uint32_t bh[2][2], bl[2][2], t[4];
                ldsm_x4(t, bd);
                bh[0][0] = t[0]; bh[0][1] = t[1]; bh[1][0] = t[2]; bh[1][1] = t[3];
                ldsm_x4(t, bd + 8192);
                bl[0][0] = t[0]; bl[0][1] = t[1]; bl[1][0] = t[2]; bl[1][1] = t[3];
                #pragma unroll
                for (int mt = 0; mt < 2; mt++)
                    #pragma unroll
                    for (int h = 0; h < 2; h++) {
                        const int nt = g * 2 + h;
                        mma16816(acc[mt][nt], ah[mt], bh[h]);
                        mma16816(acc[mt][nt], ah[mt], bl[h]);
                        mma16816(acc[mt][nt], al[mt], bh[h]);
                    }
            }
        }
    }

    // ---- epilogue: S = acc * mask
    const float* Mk = mask_ + (size_t)bz * Nn * Mm;
    float* Sp = S_ + (size_t)bz * Nn * Mm;
    const int grb = tR * 128 + m0;
    const int gcb = tC * 128 + n0;
    #pragma unroll
    for (int mt = 0; mt < 2; mt++) {
        #pragma unroll
        for (int rr = 0; rr < 2; rr++) {
            const int row = grb + mt * 16 + rr * 8 + (lane >> 2);
            #pragma unroll
            for (int nt = 0; nt < 8; nt++) {
                const int col = gcb + nt * 8 + 2 * (lane & 3);
                const float2 mk = *(const float2*)&Mk[(size_t)row * Mm + col];
                *(float2*)&Sp[(size_t)row * Mm + col] =
                    make_float2(acc[mt][nt][rr * 2 + 0] * mk.x,
                                acc[mt][nt][rr * 2 + 1] * mk.y);
            }
        }
    }
}

// ---------------- split-fp16 GEMM via mma.sync (Vf & PV/fc; R7 config) ------
// CTA tile: 128(M) x 64(N), K-step 32, 3-stage cp.async, 64B-row swizzle.
// EPI: 1 = +bias->f32 ; 2 = relu(+bias)->fp16 ; 3 = dec*(1+tanh)->fp16
template <int EPI, int AS>
__global__ __launch_bounds__(256) void gemm_mma(
    const fp16* __restrict__ Ah, const fp16* __restrict__ Al,
    const fp16* __restrict__ Bh,
    int Kd, size_t a_bs, size_t b_bs,
    const float* __restrict__ e0, size_t e0_bs, int e0_ld,
    float* __restrict__ outf, fp16* __restrict__ outh,
    size_t o_bs, int o_ld)
{
    constexpr int ACOMP = 8192;                    // 128 rows x 64 B
    constexpr int BCOMP = 4096;                    // 64 rows x 64 B
    constexpr int ABYTES = (1 + AS) * ACOMP;
    constexpr int STAGE = ABYTES + BCOMP;

    extern __shared__ char smem[];
    const uint32_t sb = smem_u32(smem);
    const int tid = threadIdx.x;
    const int wid = tid >> 5, lane = tid & 31;
    const int tC = blockIdx.x, tR = blockIdx.y, bz = blockIdx.z;
    const int NK = Kd >> 5;

    const fp16* A0h = Ah + (size_t)bz * a_bs + (size_t)(tR * 128) * Kd;
    const fp16* A0l = AS ? (Al + (size_t)bz * a_bs + (size_t)(tR * 128) * Kd) : nullptr;
    const fp16* B0h = Bh + (size_t)bz * b_bs + (size_t)(tC * 64) * Kd;

    auto load_stage = [&](int ks, int st) {
        const uint32_t base = sb + st * STAGE;
        const int k0 = ks * 32;
        #pragma unroll
        for (int j = 0; j < 2; j++) {
            const int id = tid + j * 256;
            const int r = id >> 2, c = id & 3;
            const size_t go = (size_t)r * Kd + k0 + c * 8;
            const uint32_t sw = sw64(r, c);
            cp_async16(base + sw, A0h + go);
            if (AS) cp_async16(base + ACOMP + sw, A0l + go);
        }
        {
            const int r = tid >> 2, c = tid & 3;
            cp_async16(base + ABYTES + sw64(r, c), B0h + (size_t)r * Kd + k0 + c * 8);
        }
        cp_commit();
    };

    const int m0 = (wid & 3) * 32;      // 4 warps over 128 rows
    const int n0 = (wid >> 2) * 32;     // 2 warps over 64 cols

    float acc[2][4][4];
    #pragma unroll
    for (int mt = 0; mt < 2; mt++)
        #pragma unroll
        for (int nt = 0; nt < 4; nt++)
            #pragma unroll
            for (int q = 0; q < 4; q++) acc[mt][nt][q] = 0.f;

    load_stage(0, 0);
    load_stage(1, 1);

    for (int ks = 0; ks < NK; ks++) {
        if (ks + 1 < NK) cp_wait<1>(); else cp_wait<0>();
        __syncthreads();
        if (ks + 2 < NK) load_stage(ks + 2, (ks + 2) % 3);

        const uint32_t base = sb + (ks % 3) * STAGE;
        #pragma unroll
        for (int kk = 0; kk < 2; kk++) {
            const int c0 = kk * 2;
            uint32_t ah[2][4], al[2][4], bh[4][2];
            #pragma unroll
            for (int mt = 0; mt < 2; mt++) {
                const int row = m0 + mt * 16 + (lane & 15);
                const int ch = c0 + (lane >> 4);
                const uint32_t ad = base + sw64(row, ch);
                ldsm_x4(ah[mt], ad);
                if (AS) ldsm_x4(al[mt], ad + ACOMP);
            }
            #pragma unroll
            for (int g = 0; g < 2; g++) {
                const int row = n0 + g * 16 + ((lane >> 4) << 3) + (lane & 7);
                const int ch = c0 + ((lane >> 3) & 1);
                uint32_t t[4];
                ldsm_x4(t, base + ABYTES + sw64(row, ch));
                bh[g * 2][0] = t[0]; bh[g * 2][1] = t[1];
                bh[g * 2 + 1][0] = t[2]; bh[g * 2 + 1][1] = t[3];
            }
            #pragma unroll
            for (int mt = 0; mt < 2; mt++)
                #pragma unroll
                for (int nt = 0; nt < 4; nt++) {
                    mma16816(acc[mt][nt], ah[mt], bh[nt]);
                    if (AS) mma16816(acc[mt][nt], al[mt], bh[nt]);
                }
        }
    }

    // ---- epilogue
    const int grb = tR * 128 + m0;
    const int gcb = tC * 64 + n0;
    #pragma unroll
    for (int mt = 0; mt < 2; mt++) {
        #pragma unroll
        for (int rr = 0; rr < 2; rr++) {
            const int row = grb + mt * 16 + rr * 8 + (lane >> 2);
            #pragma unroll
            for (int nt = 0; nt < 4; nt++) {
                const int col = gcb + nt * 8 + 2 * (lane & 3);
                float v0 = acc[mt][nt][rr * 2 + 0];
                float v1 = acc[mt][nt][rr * 2 + 1];
                if (EPI == 1) {
                    const float2 b = *(const float2*)&e0[col];
                    *(float2*)&outf[(size_t)bz * o_bs + (size_t)row * o_ld + col] =
                        make_float2(v0 + b.x, v1 + b.y);
                } else if (EPI == 2) {
                    const float2 b = *(const float2*)&e0[col];
                    float g0 = fmaxf(v0 + b.x, 0.f), g1 = fmaxf(v1 + b.y, 0.f);
                    *(__half2*)&outh[(size_t)bz * o_bs + (size_t)row * o_ld + col] =
                        __half2(__float2half_rn(g0), __float2half_rn(g1));
                } else {
                    const float2 dd = *(const float2*)&e0[(size_t)bz * e0_bs + (size_t)row * e0_ld + col];
                    float g0 = dd.x * (1.f + tanh_approx(v0));
                    float g1 = dd.y * (1.f + tanh_approx(v1));
                    *(__half2*)&outh[(size_t)bz * o_bs + (size_t)row * o_ld + col] =
                        __half2(__float2half_rn(g0), __float2half_rn(g1));
                }
            }
        }
    }
}

// ---------------- host launch ----------------
extern "C" void kernel_launch(void* const* d_in, const int* in_sizes, int n_in,
                              void* d_out, int out_size)
{
    const float* dec  = (const float*)d_in[0];
    const float* enc  = (const float*)d_in[1];
    const float* mask = (const float*)d_in[2];
    const float* Wv   = (const float*)d_in[3];
    const float* bv   = (const float*)d_in[4];
    const float* W1   = (const float*)d_in[5];
    const float* b1   = (const float*)d_in[6];
    const float* W2   = (const float*)d_in[7];
    const float* b2   = (const float*)d_in[8];
    float* out = (float*)d_out;

    float *S, *Vf;
    fp16 *P, *dch, *dcl, *ech, *ecl, *VT, *G, *H;
    fp16 *WvT, *W1T, *W2T;
    cudaGetSymbolAddress((void**)&S, S_buf);
    cudaGetSymbolAddress((void**)&Vf, Vf_buf);
    cudaGetSymbolAddress((void**)&P, P_buf);
    cudaGetSymbolAddress((void**)&dch, dech_buf); cudaGetSymbolAddress((void**)&dcl, decl_buf);
    cudaGetSymbolAddress((void**)&ech, ench_buf); cudaGetSymbolAddress((void**)&ecl, encl_buf);
    cudaGetSymbolAddress((void**)&VT, VT_buf);
    cudaGetSymbolAddress((void**)&G, G_buf);     cudaGetSymbolAddress((void**)&H, H_buf);
    cudaGetSymbolAddress((void**)&WvT, WvT_buf);
    cudaGetSymbolAddress((void**)&W1T, W1T_buf);
    cudaGetSymbolAddress((void**)&W2T, W2T_buf);

    // Lazy host-side stream/events (created on the first, uncaptured call).
    static cudaStream_t sB = nullptr;
    static cudaEvent_t evFork = nullptr, evJoin = nullptr;
    if (!sB) {
        cudaStreamCreateWithFlags(&sB, cudaStreamNonBlocking);
        cudaEventCreateWithFlags(&evFork, cudaEventDisableTiming);
        cudaEventCreateWithFlags(&evJoin, cudaEventDisableTiming);
    }

    // smem footprints
    constexpr int SM_A  = 3 * (2 * 8192 + 4096);   // Vf (AS=1)
    constexpr int SM_00 = 3 * (8192 + 4096);       // PV/fc (AS=0)
    cudaFuncSetAttribute(score128,      cudaFuncAttributeMaxDynamicSharedMemorySize, SM_SC);
    cudaFuncSetAttribute(gemm_mma<1,1>, cudaFuncAttributeMaxDynamicSharedMemorySize, SM_A);
    cudaFuncSetAttribute(gemm_mma<3,0>, cudaFuncAttributeMaxDynamicSharedMemorySize, SM_00);
    cudaFuncSetAttribute(gemm_mma<2,0>, cudaFuncAttributeMaxDynamicSharedMemorySize, SM_00);
    cudaFuncSetAttribute(gemm_mma<1,0>, cudaFuncAttributeMaxDynamicSharedMemorySize, SM_00);

    const size_t nEmb = (size_t)Bb * Nn * Cc;       // 8M elems
    dim3 tb(32, 8);

    // 1) split dec & enc to fp16 hi/lo (origin stream)
    split2_kernel<<<dim3((unsigned)(nEmb / 4 / 256), 2), 256>>>(
        dec, dch, dcl, enc, ech, ecl, nEmb / 4);

    // ---- fork: side stream runs the V-producer chain + weight transposes
    cudaEventRecord(evFork, 0);
    cudaStreamWaitEvent(sB, evFork, 0);

    transpose_fp16<<<dim3(Cc / 32, Cc / 32, 1), tb, 0, sB>>>(Wv, WvT, Cc, Cc, 0, 0);
    transpose_fp16<<<dim3(Cc / 32, Cc / 32, 1), tb, 0, sB>>>(W1, W1T, Cc, Cc, 0, 0);
    transpose_fp16<<<dim3(Cc / 32, Cc / 32, 1), tb, 0, sB>>>(W2, W2T, Cc, Cc, 0, 0);

    // Vf = enc @ Wv + bv (fp32): A=enc split, B=WvT single
    gemm_mma<1,1><<<dim3(Cc / 64, (Bb * Mm) / 128, 1), 256, SM_A, sB>>>(
        ech, ecl, WvT, Cc, 0, 0,
        bv, 0, 0, Vf, nullptr, 0, Cc);

    // VT = transpose(Vf) -> fp16 single  [B][C][M]
    transpose_fp16<<<dim3(Cc / 32, Mm / 32, Bb), tb, 0, sB>>>(
        Vf, VT, Mm, Cc, (size_t)Mm * Cc, (size_t)Cc * Mm);

    cudaEventRecord(evJoin, sB);

    // ---- origin stream: scores (128x128 tile) + softmax
    score128<<<dim3(Mm / 128, Nn / 128, Bb), 256, SM_SC>>>(
        dch, dcl, ech, ecl, mask, S);

    softmax_kernel<<<Bb * Nn, 256>>>(S, P);

    // ---- join: PV needs VT
    cudaStreamWaitEvent(0, evJoin, 0);

    // G = dec * (1 + tanh(P @ V)) -> fp16: single x single
    gemm_mma<3,0><<<dim3(Cc / 64, Nn / 128, Bb), 256, SM_00>>>(
        P, nullptr, VT, Mm, (size_t)Nn * Mm, (size_t)Cc * Mm,
        dec, (size_t)Nn * Cc, Cc, nullptr, G, (size_t)Nn * Cc, Cc);

    // H = relu(G @ W1 + b1) -> fp16
    gemm_mma<2,0><<<dim3(Cc / 64, (Bb * Nn) / 128, 1), 256, SM_00>>>(
        G, nullptr, W1T, Cc, 0, 0,
        b1, 0, 0, nullptr, H, 0, Cc);

    // out = H @ W2 + b2 (fp32)
    gemm_mma<1,0><<<dim3(Cc / 64, (Bb * Nn) / 128, 1), 256, SM_00>>>(
        H, nullptr, W2T, Cc, 0, 0,
        b2, 0, 0, out, nullptr, 0, Cc);
}

// round 15
// speedup vs baseline: 1.0718x; 1.0718x over previous
#include <cuda_runtime.h>
#include <cuda_fp16.h>
#include <cstdint>
#include <math.h>

typedef __half fp16;

static constexpr int Bb = 8, Nn = 2048, Mm = 2048, Cc = 512;

// ---------------- scratch (__device__ globals; no allocations) ----------------
__device__ float S_buf [(size_t)Bb * Nn * Mm];          // scores fp32 (128 MiB)
__device__ fp16  P_buf [(size_t)Bb * Nn * Mm];          // softmax probs (single fp16)
__device__ fp16  dech_buf[(size_t)Bb * Nn * Cc], decl_buf[(size_t)Bb * Nn * Cc];
__device__ fp16  ench_buf[(size_t)Bb * Mm * Cc], encl_buf[(size_t)Bb * Mm * Cc];
__device__ float Vf_buf [(size_t)Bb * Mm * Cc];         // enc@Wv+bv fp32
__device__ fp16  VT_buf [(size_t)Bb * Cc * Mm];         // V^T single fp16
__device__ fp16  G_buf[(size_t)Bb * Nn * Cc];           // gated, single fp16
__device__ fp16  H_buf[(size_t)Bb * Nn * Cc];           // relu(fc1), single fp16
__device__ fp16  WvT_buf[Cc * Cc];
__device__ fp16  W1T_buf[Cc * Cc];
__device__ fp16  W2T_buf[Cc * Cc];

// ---------------- arch-neutral PTX helpers ----------------
__device__ __forceinline__ uint32_t smem_u32(const void* p) {
    uint32_t a;
    asm("{ .reg .u64 t; cvta.to.shared.u64 t, %1; cvt.u32.u64 %0, t; }" : "=r"(a) : "l"(p));
    return a;
}
__device__ __forceinline__ void cp_async16(uint32_t dst, const void* src) {
    asm volatile("cp.async.cg.shared.global [%0], [%1], 16;" :: "r"(dst), "l"(src) : "memory");
}
__device__ __forceinline__ void cp_commit() { asm volatile("cp.async.commit_group;" ::: "memory"); }
template <int N> __device__ __forceinline__ void cp_wait() {
    asm volatile("cp.async.wait_group %0;" :: "n"(N) : "memory");
}
__device__ __forceinline__ void ldsm_x4(uint32_t* r, uint32_t addr) {
    asm volatile("ldmatrix.sync.aligned.m8n8.x4.shared.b16 {%0,%1,%2,%3}, [%4];"
        : "=r"(r[0]), "=r"(r[1]), "=r"(r[2]), "=r"(r[3]) : "r"(addr));
}
__device__ __forceinline__ void mma16816(float* c, const uint32_t* a, const uint32_t* b) {
    asm volatile("mma.sync.aligned.m16n8k16.row.col.f32.f16.f16.f32 "
        "{%0,%1,%2,%3}, {%4,%5,%6,%7}, {%8,%9}, {%0,%1,%2,%3};"
        : "+f"(c[0]), "+f"(c[1]), "+f"(c[2]), "+f"(c[3])
        : "r"(a[0]), "r"(a[1]), "r"(a[2]), "r"(a[3]), "r"(b[0]), "r"(b[1]));
}
__device__ __forceinline__ float tanh_approx(float x) {
    float r;
    asm("tanh.approx.f32 %0, %1;" : "=f"(r) : "f"(x));
    return r;
}
// 64B-row swizzle: logical chunk c (0..3) of row r -> phys chunk c ^ ((r>>1)&3)
__device__ __forceinline__ uint32_t sw64(int r, int c) {
    return (uint32_t)r * 64u + (uint32_t)((c ^ ((r >> 1) & 3)) << 4);
}

// ---------------- conversion / transpose kernels ----------------
__global__ void split2_kernel(const float* __restrict__ inA, fp16* __restrict__ ohA, fp16* __restrict__ olA,
                              const float* __restrict__ inB, fp16* __restrict__ ohB, fp16* __restrict__ olB,
                              size_t n4) {
    size_t i = (size_t)blockIdx.x * blockDim.x + threadIdx.x;
    if (i >= n4) return;
    const float* in = blockIdx.y ? inB : inA;
    fp16* oh = blockIdx.y ? ohB : ohA;
    fp16* ol = blockIdx.y ? olB : olA;
    float4 v = ((const float4*)in)[i];
    fp16 h0 = __float2half_rn(v.x), h1 = __float2half_rn(v.y);
    fp16 h2 = __float2half_rn(v.z), h3 = __float2half_rn(v.w);
    ((__half2*)oh)[2 * i]     = __half2(h0, h1);
    ((__half2*)oh)[2 * i + 1] = __half2(h2, h3);
    ((__half2*)ol)[2 * i] = __half2(
        __float2half_rn(v.x - __half2float(h0)), __float2half_rn(v.y - __half2float(h1)));
    ((__half2*)ol)[2 * i + 1] = __half2(
        __float2half_rn(v.z - __half2float(h2)), __float2half_rn(v.w - __half2float(h3)));
}

// out[c][r] = in[r][c]
__global__ void transpose_fp16(const float* __restrict__ in, fp16* __restrict__ oh,
                               int rows, int cols, size_t ibs, size_t obs) {
    __shared__ float t[32][33];
    const float* I = in + (size_t)blockIdx.z * ibs;
    fp16* OH = oh + (size_t)blockIdx.z * obs;
    int c0 = blockIdx.x * 32, r0 = blockIdx.y * 32;
    int tx = threadIdx.x, ty = threadIdx.y;
    #pragma unroll
    for (int k = 0; k < 4; k++)
        t[ty + 8 * k][tx] = I[(size_t)(r0 + ty + 8 * k) * cols + c0 + tx];
    __syncthreads();
    #pragma unroll
    for (int k = 0; k < 4; k++) {
        float v = t[tx][ty + 8 * k];
        OH[(size_t)(c0 + ty + 8 * k) * rows + r0 + tx] = __float2half_rn(v);
    }
}

// ---------------- nonstandard masked softmax: S fp32 -> P fp16 ----------------
__global__ __launch_bounds__(256) void softmax_kernel(const float* __restrict__ Sb,
                                                      fp16* __restrict__ Pp) {
    const float* S = Sb + (size_t)blockIdx.x * Mm;
    fp16* P = Pp + (size_t)blockIdx.x * Mm;
    const int tid = threadIdx.x;

    float4 u0 = *(const float4*)&S[tid * 8];
    float4 u1 = *(const float4*)&S[tid * 8 + 4];
    float v[8] = {u0.x, u0.y, u0.z, u0.w, u1.x, u1.y, u1.z, u1.w};

    float mx = v[0];
    #pragma unroll
    for (int i = 1; i < 8; i++) mx = fmaxf(mx, v[i]);
    #pragma unroll
    for (int o = 16; o > 0; o >>= 1) mx = fmaxf(mx, __shfl_xor_sync(0xffffffffu, mx, o));

    __shared__ float red[8];
    const int wid = tid >> 5, lid = tid & 31;
    if (lid == 0) red[wid] = mx;
    __syncthreads();
    float rmax = red[0];
    #pragma unroll
    for (int w = 1; w < 8; w++) rmax = fmaxf(rmax, red[w]);
    __syncthreads();

    float e[8];
    float s = 0.f;
    #pragma unroll
    for (int i = 0; i < 8; i++) { e[i] = __expf(v[i] - rmax); s += e[i]; }
    #pragma unroll
    for (int o = 16; o > 0; o >>= 1) s += __shfl_xor_sync(0xffffffffu, s, o);
    if (lid == 0) red[wid] = s;
    __syncthreads();
    float tot = 0.f;
    #pragma unroll
    for (int w = 0; w < 8; w++) tot += red[w];
    const float inv = 1.f / tot;

    fp16 p[8];
    #pragma unroll
    for (int i = 0; i < 8; i++)
        p[i] = __float2half_rn((v[i] != 0.f) ? e[i] * inv : 0.f);
    *(uint4*)&P[tid * 8] = *(uint4*)p;
}

// ---------------- split-fp16 GEMM via mma.sync (R7 configuration) -----------
// CTA tile: 128(M) x 64(N), K-step 32, 3-stage cp.async pipeline, 64B-row swizzle.
// A: [rows][K] hi (+lo if AS). B: [cols][K] hi (+lo if BS). C = A x B^T.
// Terms: Ah*Bh (+Ah*Bl if BS) (+Al*Bh if AS), all fp32 accumulate.
// EPI: 0 = *mask->f32 ; 1 = +bias->f32 ; 2 = relu(+bias)->fp16 ; 3 = dec*(1+tanh)->fp16
template <int EPI, int AS, int BS>
__global__ __launch_bounds__(256) void gemm_mma(
    const fp16* __restrict__ Ah, const fp16* __restrict__ Al,
    const fp16* __restrict__ Bh, const fp16* __restrict__ Bl,
    int Kd, size_t a_bs, size_t b_bs,
    const float* __restrict__ e0, size_t e0_bs, int e0_ld,
    float* __restrict__ outf, fp16* __restrict__ outh,
    size_t o_bs, int o_ld)
{
    constexpr int ACOMP = 8192;                    // 128 rows x 64 B
    constexpr int BCOMP = 4096;                    // 64 rows x 64 B
    constexpr int ABYTES = (1 + AS) * ACOMP;
    constexpr int STAGE = ABYTES + (1 + BS) * BCOMP;

    extern __shared__ char smem[];
    const uint32_t sb = smem_u32(smem);
    const int tid = threadIdx.x;
    const int wid = tid >> 5, lane = tid & 31;
    const int tC = blockIdx.x, tR = blockIdx.y, bz = blockIdx.z;
    const int NK = Kd >> 5;

    const fp16* A0h = Ah + (size_t)bz * a_bs + (size_t)(tR * 128) * Kd;
    const fp16* A0l = AS ? (Al + (size_t)bz * a_bs + (size_t)(tR * 128) * Kd) : nullptr;
    const fp16* B0h = Bh + (size_t)bz * b_bs + (size_t)(tC * 64) * Kd;
    const fp16* B0l = BS ? (Bl + (size_t)bz * b_bs + (size_t)(tC * 64) * Kd) : nullptr;

    auto load_stage = [&](int ks, int st) {
        const uint32_t base = sb + st * STAGE;
        const int k0 = ks * 32;
        #pragma unroll
        for (int j = 0; j < 2; j++) {
            const int id = tid + j * 256;
            const int r = id >> 2, c = id & 3;
            const size_t go = (size_t)r * Kd + k0 + c * 8;
            const uint32_t sw = sw64(r, c);
            cp_async16(base + sw, A0h + go);
            if (AS) cp_async16(base + ACOMP + sw, A0l + go);
        }
        {
            const int r = tid >> 2, c = tid & 3;
            const size_t go = (size_t)r * Kd + k0 + c * 8;
            const uint32_t sw = sw64(r, c);
            cp_async16(base + ABYTES + sw, B0h + go);
            if (BS) cp_async16(base + ABYTES + BCOMP + sw, B0l + go);
        }
        cp_commit();
    };

    const int m0 = (wid & 3) * 32;      // warp row offset (4 warps over 128 rows)
    const int n0 = (wid >> 2) * 32;     // warp col offset (2 warps over 64 cols)

    float acc[2][4][4];
    #pragma unroll
    for (int mt = 0; mt < 2; mt++)
        #pragma unroll
        for (int nt = 0; nt < 4; nt++)
            #pragma unroll
            for (int q = 0; q < 4; q++) acc[mt][nt][q] = 0.f;

    load_stage(0, 0);
    load_stage(1, 1);

    for (int ks = 0; ks < NK; ks++) {
        if (ks + 1 < NK) cp_wait<1>(); else cp_wait<0>();
        __syncthreads();
        if (ks + 2 < NK) load_stage(ks + 2, (ks + 2) % 3);

        const uint32_t base = sb + (ks % 3) * STAGE;
        #pragma unroll
        for (int kk = 0; kk < 2; kk++) {
            const int c0 = kk * 2;
            uint32_t ah[2][4], al[2][4], bh[4][2], bl[4][2];
            #pragma unroll
            for (int mt = 0; mt < 2; mt++) {
                const int row = m0 + mt * 16 + (lane & 15);
                const int ch = c0 + (lane >> 4);
                const uint32_t ad = base + sw64(row, ch);
                ldsm_x4(ah[mt], ad);
                if (AS) ldsm_x4(al[mt], ad + ACOMP);
            }
            #pragma unroll
            for (int g = 0; g < 2; g++) {
                const int row = n0 + g * 16 + ((lane >> 4) << 3) + (lane & 7);
                const int ch = c0 + ((lane >> 3) & 1);
                const uint32_t bd = base + ABYTES + sw64(row, ch);
                uint32_t t[4];
                ldsm_x4(t, bd);
                bh[g * 2][0] = t[0]; bh[g * 2][1] = t[1];
                bh[g * 2 + 1][0] = t[2]; bh[g * 2 + 1][1] = t[3];
                if (BS) {
                    ldsm_x4(t, bd + BCOMP);
                    bl[g * 2][0] = t[0]; bl[g * 2][1] = t[1];
                    bl[g * 2 + 1][0] = t[2]; bl[g * 2 + 1][1] = t[3];
                }
            }
            #pragma unroll
            for (int mt = 0; mt < 2; mt++)
                #pragma unroll
                for (int nt = 0; nt < 4; nt++) {
                    mma16816(acc[mt][nt], ah[mt], bh[nt]);
                    if (BS) mma16816(acc[mt][nt], ah[mt], bl[nt]);
                    if (AS) mma16816(acc[mt][nt], al[mt], bh[nt]);
                }
        }
    }

    // ---- epilogue
    const int grb = tR * 128 + m0;
    const int gcb = tC * 64 + n0;
    #pragma unroll
    for (int mt = 0; mt < 2; mt++) {
        #pragma unroll
        for (int rr = 0; rr < 2; rr++) {
            const int row = grb + mt * 16 + rr * 8 + (lane >> 2);
            #pragma unroll
            for (int nt = 0; nt < 4; nt++) {
                const int col = gcb + nt * 8 + 2 * (lane & 3);
                float v0 = acc[mt][nt][rr * 2 + 0];
                float v1 = acc[mt][nt][rr * 2 + 1];
                if (EPI == 0) {
                    const float2 mk = *(const float2*)&e0[(size_t)bz * e0_bs + (size_t)row * e0_ld + col];
                    *(float2*)&outf[(size_t)bz * o_bs + (size_t)row * o_ld + col] =
                        make_float2(v0 * mk.x, v1 * mk.y);
                } else if (EPI == 1) {
                    const float2 b = *(const float2*)&e0[col];
                    *(float2*)&outf[(size_t)bz * o_bs + (size_t)row * o_ld + col] =
                        make_float2(v0 + b.x, v1 + b.y);
                } else if (EPI == 2) {
                    const float2 b = *(const float2*)&e0[col];
                    float g0 = fmaxf(v0 + b.x, 0.f), g1 = fmaxf(v1 + b.y, 0.f);
                    *(__half2*)&outh[(size_t)bz * o_bs + (size_t)row * o_ld + col] =
                        __half2(__float2half_rn(g0), __float2half_rn(g1));
                } else {
                    const float2 dd = *(const float2*)&e0[(size_t)bz * e0_bs + (size_t)row * e0_ld + col];
                    float g0 = dd.x * (1.f + tanh_approx(v0));
                    float g1 = dd.y * (1.f + tanh_approx(v1));
                    *(__half2*)&outh[(size_t)bz * o_bs + (size_t)row * o_ld + col] =
                        __half2(__float2half_rn(g0), __float2half_rn(g1));
                }
            }
        }
    }
}

// ---------------- host launch ----------------
extern "C" void kernel_launch(void* const* d_in, const int* in_sizes, int n_in,
                              void* d_out, int out_size)
{
    const float* dec  = (const float*)d_in[0];
    const float* enc  = (const float*)d_in[1];
    const float* mask = (const float*)d_in[2];
    const float* Wv   = (const float*)d_in[3];
    const float* bv   = (const float*)d_in[4];
    const float* W1   = (const float*)d_in[5];
    const float* b1   = (const float*)d_in[6];
    const float* W2   = (const float*)d_in[7];
    const float* b2   = (const float*)d_in[8];
    float* out = (float*)d_out;

    float *S, *Vf;
    fp16 *P, *dch, *dcl, *ech, *ecl, *VT, *G, *H;
    fp16 *WvT, *W1T, *W2T;
    cudaGetSymbolAddress((void**)&S, S_buf);
    cudaGetSymbolAddress((void**)&Vf, Vf_buf);
    cudaGetSymbolAddress((void**)&P, P_buf);
    cudaGetSymbolAddress((void**)&dch, dech_buf); cudaGetSymbolAddress((void**)&dcl, decl_buf);
    cudaGetSymbolAddress((void**)&ech, ench_buf); cudaGetSymbolAddress((void**)&ecl, encl_buf);
    cudaGetSymbolAddress((void**)&VT, VT_buf);
    cudaGetSymbolAddress((void**)&G, G_buf);     cudaGetSymbolAddress((void**)&H, H_buf);
    cudaGetSymbolAddress((void**)&WvT, WvT_buf);
    cudaGetSymbolAddress((void**)&W1T, W1T_buf);
    cudaGetSymbolAddress((void**)&W2T, W2T_buf);

    // Lazy host-side stream/events (created on the first, uncaptured call).
    static cudaStream_t sB = nullptr;
    static cudaEvent_t evFork = nullptr, evJoin = nullptr;
    if (!sB) {
        cudaStreamCreateWithFlags(&sB, cudaStreamNonBlocking);
        cudaEventCreateWithFlags(&evFork, cudaEventDisableTiming);
        cudaEventCreateWithFlags(&evJoin, cudaEventDisableTiming);
    }

    // 3-stage smem footprints
    constexpr int SM_3T = 3 * (2 * 8192 + 2 * 4096);   // scores (AS=1,BS=1)
    constexpr int SM_A  = 3 * (2 * 8192 + 1 * 4096);   // Vf (AS=1,BS=0)
    constexpr int SM_00 = 3 * (1 * 8192 + 1 * 4096);   // PV/fc (AS=0,BS=0)
    cudaFuncSetAttribute(gemm_mma<0,1,1>, cudaFuncAttributeMaxDynamicSharedMemorySize, SM_3T);
    cudaFuncSetAttribute(gemm_mma<1,1,0>, cudaFuncAttributeMaxDynamicSharedMemorySize, SM_A);
    cudaFuncSetAttribute(gemm_mma<3,0,0>, cudaFuncAttributeMaxDynamicSharedMemorySize, SM_00);
    cudaFuncSetAttribute(gemm_mma<2,0,0>, cudaFuncAttributeMaxDynamicSharedMemorySize, SM_00);
    cudaFuncSetAttribute(gemm_mma<1,0,0>, cudaFuncAttributeMaxDynamicSharedMemorySize, SM_00);

    const size_t nEmb = (size_t)Bb * Nn * Cc;       // 8M elems
    dim3 tb(32, 8);

    // 1) split dec & enc to fp16 hi/lo (origin stream)
    split2_kernel<<<dim3((unsigned)(nEmb / 4 / 256), 2), 256>>>(
        dec, dch, dcl, enc, ech, ecl, nEmb / 4);

    // ---- fork: side stream runs the V-producer chain + weight transposes
    cudaEventRecord(evFork, 0);
    cudaStreamWaitEvent(sB, evFork, 0);

    transpose_fp16<<<dim3(Cc / 32, Cc / 32, 1), tb, 0, sB>>>(Wv, WvT, Cc, Cc, 0, 0);
    transpose_fp16<<<dim3(Cc / 32, Cc / 32, 1), tb, 0, sB>>>(W1, W1T, Cc, Cc, 0, 0);
    transpose_fp16<<<dim3(Cc / 32, Cc / 32, 1), tb, 0, sB>>>(W2, W2T, Cc, Cc, 0, 0);

    // Vf = enc @ Wv + bv (fp32): A=enc split, B=WvT single
    gemm_mma<1,1,0><<<dim3(Cc / 64, (Bb * Mm) / 128, 1), 256, SM_A, sB>>>(
        ech, ecl, WvT, nullptr, Cc, 0, 0,
        bv, 0, 0, Vf, nullptr, 0, Cc);

    // VT = transpose(Vf) -> fp16 single  [B][C][M]
    transpose_fp16<<<dim3(Cc / 32, Mm / 32, Bb), tb, 0, sB>>>(
        Vf, VT, Mm, Cc, (size_t)Mm * Cc, (size_t)Cc * Mm);

    cudaEventRecord(evJoin, sB);

    // ---- origin stream: scores + softmax (overlaps with side stream)
    gemm_mma<0,1,1><<<dim3(Mm / 64, Nn / 128, Bb), 256, SM_3T>>>(
        dch, dcl, ech, ecl, Cc, (size_t)Nn * Cc, (size_t)Mm * Cc,
        mask, (size_t)Nn * Mm, Mm, S, nullptr, (size_t)Nn * Mm, Mm);

    softmax_kernel<<<Bb * Nn, 256>>>(S, P);

    // ---- join: PV needs VT
    cudaStreamWaitEvent(0, evJoin, 0);

    // G = dec * (1 + tanh(P @ V)) -> fp16: single x single
    gemm_mma<3,0,0><<<dim3(Cc / 64, Nn / 128, Bb), 256, SM_00>>>(
        P, nullptr, VT, nullptr, Mm, (size_t)Nn * Mm, (size_t)Cc * Mm,
        dec, (size_t)Nn * Cc, Cc, nullptr, G, (size_t)Nn * Cc, Cc);

    // H = relu(G @ W1 + b1) -> fp16
    gemm_mma<2,0,0><<<dim3(Cc / 64, (Bb * Nn) / 128, 1), 256, SM_00>>>(
        G, nullptr, W1T, nullptr, Cc, 0, 0,
        b1, 0, 0, nullptr, H, 0, Cc);

    // out = H @ W2 + b2 (fp32)
    gemm_mma<1,0,0><<<dim3(Cc / 64, (Bb * Nn) / 128, 1), 256, SM_00>>>(
        H, nullptr, W2T, nullptr, Cc, 0, 0,
        b2, 0, 0, out, nullptr, 0, Cc);
}